// round 10
// baseline (speedup 1.0000x reference)
#include <cuda_runtime.h>

// ---------------------------------------------------------------------------
// ISTFT fused: B=16, NFREQ=513, T=2048, NFFT=1024, HOP=256, WIN=1024, PAD=384
// Kernel A: zero exactly the atomic-stripe samples (compact index mapping).
// Kernel B: 8 frames/block. Pair-loaded Hermitian packing (mirror output is
//           algebraically free; 4-complex cross-worker exchange via a small
//           conflict-free smem buffer), 3-stage radix-8 Stockham inverse FFT
//           (float2 shared, register twiddles), windowed frames in shared,
//           overlap-add direct to out (interior stores, stripe atomicAdds,
//           explicit envelope at batch edges). No global scratch.
// ---------------------------------------------------------------------------

#define BATCH     16
#define NFREQ     513
#define TT        2048
#define NFFT      1024
#define HOP       256
#define PAD       384
#define OUT_PER_B 524288                 // (T-1)*HOP + WIN - 2*PAD = 1<<19
#define NFRAMES   (BATCH * TT)           // 32768
#define FPB       8                      // frames per block
#define YPITCH    1028                   // 1028 % 32 == 4 -> bank-perm rows

#define SM_FLOATS (8224 + 4096)          // y/A overlay region + ex buffer
#define SM_BYTES  (SM_FLOATS * 4)        // 49280 bytes -> 4 blocks/SM

// conflict-free shared index (float2 units): phi(pos) = pos ^ (pos>>3)
__device__ __forceinline__ int sidx(int pos, int f) {
    return ((pos ^ (pos >> 3)) << 3) | f;
}

// radix-8 butterfly on 8 complex registers (inverse FFT, +i convention)
__device__ __forceinline__ void bfly8(const float* xr, const float* xi,
                                      float* Xr, float* Xi)
{
    float e0r = xr[0] + xr[4], e0i = xi[0] + xi[4];
    float e1r = xr[0] - xr[4], e1i = xi[0] - xi[4];
    float e2r = xr[2] + xr[6], e2i = xi[2] + xi[6];
    float e3r = xr[2] - xr[6], e3i = xi[2] - xi[6];
    float E0r = e0r + e2r, E0i = e0i + e2i;
    float E2r = e0r - e2r, E2i = e0i - e2i;
    float E1r = e1r - e3i, E1i = e1i + e3r;
    float E3r = e1r + e3i, E3i = e1i - e3r;

    float o0r = xr[1] + xr[5], o0i = xi[1] + xi[5];
    float o1r = xr[1] - xr[5], o1i = xi[1] - xi[5];
    float o2r = xr[3] + xr[7], o2i = xi[3] + xi[7];
    float o3r = xr[3] - xr[7], o3i = xi[3] - xi[7];
    float O0r = o0r + o2r, O0i = o0i + o2i;
    float O2r = o0r - o2r, O2i = o0i - o2i;
    float O1r = o1r - o3i, O1i = o1i + o3r;
    float O3r = o1r + o3i, O3i = o1i - o3r;

    const float RS = 0.70710678118654752440f;
    float c1r = RS * (O1r - O1i), c1i = RS * (O1r + O1i);   // e^{+i pi/4} O1
    float c2r = -O2i,             c2i = O2r;                // i * O2
    float c3r = -RS * (O3r + O3i), c3i = RS * (O3r - O3i);  // e^{+3i pi/4} O3

    Xr[0] = E0r + O0r; Xi[0] = E0i + O0i;
    Xr[4] = E0r - O0r; Xi[4] = E0i - O0i;
    Xr[1] = E1r + c1r; Xi[1] = E1i + c1i;
    Xr[5] = E1r - c1r; Xi[5] = E1i - c1i;
    Xr[2] = E2r + c2r; Xi[2] = E2i + c2i;
    Xr[6] = E2r - c2r; Xi[6] = E2i - c2i;
    Xr[3] = E3r + c3r; Xi[3] = E3i + c3i;
    Xr[7] = E3r - c3r; Xi[7] = E3i - c3i;
}

// zero exactly the stripe float4s: per batch 96 + 255*192 + 96 = 49152
__global__ void __launch_bounds__(256)
istft_zero_kernel(float4* __restrict__ out4)
{
    unsigned idx = blockIdx.x * 256u + threadIdx.x;   // < 786432
    unsigned b = idx / 49152u;
    unsigned r = idx - b * 49152u;
    unsigned o4;
    if (r < 96u) {
        o4 = r;                                       // head: o in [0,384)
    } else {
        unsigned rr = r - 96u;
        unsigned k  = rr / 192u + 1u;                 // period 1..256
        unsigned j  = rr - (k - 1u) * 192u;
        o4 = (k << 9) - 96u + j;                      // o in [2048k-384, ...)
    }
    out4[b * 131072u + o4] = make_float4(0.f, 0.f, 0.f, 0.f);
}

__global__ void __launch_bounds__(512)
istft_fused_kernel(const float* __restrict__ spr,
                   const float* __restrict__ spi,
                   const float* __restrict__ win,
                   float* __restrict__ out)
{
    extern __shared__ float sm[];
    float2* A  = (float2*)sm;           // 4096 float2 (FFT work buffer)
    float*  y  = sm;                    // frame staging overlay: 8*YPITCH
    float2* ex = (float2*)(sm + 8224);  // exchange: ex[jj<<9 | du<<3 | f]

    const int tid = threadIdx.x;
    const int f   = tid & 7;    // frame lane
    const int u   = tid >> 3;   // worker 0..63

    const int fr0 = blockIdx.x * FPB;
    const int b   = fr0 >> 11;
    const int t0  = fr0 & 2047;
    const float* pr  = spr + (size_t)b * NFREQ * TT + (t0 + f);
    const float* pim = spi + (size_t)b * NFREQ * TT + (t0 + f);

    float vr[8], vi[8];

    // ---- Hermitian packing via pair loads; mirror output is free ----
    // Z[k]     = (Er-Oi, Ei+Or)
    // Z[512-k] = (Er+Oi, Or-Ei)   -> belongs to worker (64-u), slot j=7-m
    {
        float ct, st;   // e^{+2pi i u/1024}, chained by e^{+2pi i/16}
        __sincosf((float)u * 6.1359231515e-3f, &st, &ct);
        const float S16r = 0.92387953251128675613f;
        const float S16i = 0.38268343236508977173f;
        #pragma unroll
        for (int m = 0; m < 4; m++) {
            int k  = u + (m << 6);
            int kc = 512 - k;                   // row 512 valid (Nyquist)
            float xkr = __ldg(pr  + k  * TT);
            float xki = __ldg(pim + k  * TT);
            float xcr = __ldg(pr  + kc * TT);
            float xci = __ldg(pim + kc * TT);
            if (k == 0) { xki = 0.0f; xci = 0.0f; }
            float Er = 0.5f * (xkr + xcr);
            float Ei = 0.5f * (xki - xci);
            float Dr = 0.5f * (xkr - xcr);
            float Di = 0.5f * (xki + xci);
            float Or = fmaf(ct, Dr, -st * Di);
            float Oi = fmaf(ct, Di,  st * Dr);
            vr[m] = Er - Oi;
            vi[m] = Ei + Or;
            if (!(u == 0 && m == 0)) {          // k=0 mirror (pos 512) invalid
                int jj = (u == 0) ? (4 - m) : (3 - m);
                int du = (64 - u) & 63;
                ex[(jj << 9) + (du << 3) + f] = make_float2(Er + Oi, Or - Ei);
            }
            float nc = fmaf(ct, S16r, -st * S16i);
            float ns = fmaf(ct, S16i,  st * S16r);
            ct = nc; st = ns;
        }
        if (u == 0) {                           // singleton Z[256]=conj(X[256])
            float x256r = __ldg(pr  + 256 * TT);
            float x256i = __ldg(pim + 256 * TT);
            ex[f] = make_float2(x256r, -x256i); // jj=0, du=0
        }
    }
    __syncthreads();
    #pragma unroll
    for (int jj = 0; jj < 4; jj++) {
        float2 z = ex[(jj << 9) + (u << 3) + f];
        vr[4 + jj] = z.x; vi[4 + jj] = z.y;
    }

    // ---- stage 1 (S=1): regs -> A, twiddle (e^{+2pi i u/512})^m ----
    {
        float w1r, w1i;
        __sincosf((float)u * 1.2271846303e-2f, &w1i, &w1r);
        float Xr[8], Xi[8];
        bfly8(vr, vi, Xr, Xi);
        A[sidx(8 * u, f)] = make_float2(Xr[0], Xi[0]);
        float cr = w1r, ci = w1i;
        #pragma unroll
        for (int m = 1; m < 8; m++) {
            A[sidx(8 * u + m, f)] =
                make_float2(fmaf(Xr[m], cr, -Xi[m] * ci),
                            fmaf(Xr[m], ci,  Xi[m] * cr));
            float nc = fmaf(cr, w1r, -ci * w1i);
            float ns = fmaf(cr, w1i,  ci * w1r);
            cr = nc; ci = ns;
        }
    }
    __syncthreads();

    // ---- stage 2 (S=8): A -> regs -> A, twiddle (e^{+2pi i h/64})^m ----
    {
        #pragma unroll
        for (int j = 0; j < 8; j++) {
            float2 z = A[sidx(u + (j << 6), f)];
            vr[j] = z.x; vi[j] = z.y;
        }
        __syncthreads();
        const int h = u >> 3;
        float bhr, bhi;
        __sincosf((float)h * 9.8174770424e-2f, &bhi, &bhr);
        float Xr[8], Xi[8];
        bfly8(vr, vi, Xr, Xi);
        const int wb = (u & 7) + 64 * h;
        A[sidx(wb, f)] = make_float2(Xr[0], Xi[0]);
        float cr = bhr, ci = bhi;
        #pragma unroll
        for (int m = 1; m < 8; m++) {
            A[sidx(wb + 8 * m, f)] =
                make_float2(fmaf(Xr[m], cr, -Xi[m] * ci),
                            fmaf(Xr[m], ci,  Xi[m] * cr));
            float nc = fmaf(cr, bhr, -ci * bhi);
            float ns = fmaf(cr, bhi,  ci * bhr);
            cr = nc; ci = ns;
        }
    }
    __syncthreads();

    // ---- stage 3 (S=64): A -> regs; windowed frames -> y[f][pos] ----
    #pragma unroll
    for (int j = 0; j < 8; j++) {
        float2 z = A[sidx(u + (j << 6), f)];
        vr[j] = z.x; vi[j] = z.y;
    }
    __syncthreads();   // reads done -> y may overwrite A
    {
        float Xr[8], Xi[8];
        bfly8(vr, vi, Xr, Xi);
        const float2* w2 = (const float2*)win;
        const float inv = 1.0f / 512.0f;
        float* yf = y + f * YPITCH;
        #pragma unroll
        for (int m = 0; m < 8; m++) {
            int n = u + (m << 6);
            float2 wv = __ldg(w2 + n);
            float2 o;
            o.x = Xr[m] * inv * wv.x;
            o.y = Xi[m] * inv * wv.y;
            *(float2*)(yf + 2 * n) = o;        // pos 2n, 2n+1
        }
    }
    __syncthreads();

    // =================== overlap-add from shared ===================
    float* outb = out + (size_t)b * OUT_PER_B;
    const float TW3 = 2.0f / 3.0f;

    // interior-owned: tmax in [t0+3, t0+7], l in [256(t0+3), 256(t0+8))
    #pragma unroll
    for (int s = tid; s < 1280; s += 512) {
        int l   = ((t0 + 3) << 8) + s;
        int fl  = 3 + (s >> 8);            // tmax - t0, 3..7
        int pos = s & 255;
        float acc = y[(fl - 3) * YPITCH + pos + 768]
                  + y[(fl - 2) * YPITCH + pos + 512]
                  + y[(fl - 1) * YPITCH + pos + 256]
                  + y[(fl    ) * YPITCH + pos      ];
        outb[l - PAD] = acc * TW3;
    }

    if (t0 != 0) {
        // bottom stripe: l in [256 t0, 256(t0+3))
        #pragma unroll
        for (int s = tid; s < 768; s += 512) {
            int r = s >> 8;                // tmax - t0: 0,1,2
            float acc = y[s];
            if (r >= 1) acc += y[1 * YPITCH + s - 256];
            if (r >= 2) acc += y[2 * YPITCH + s - 512];
            int l = (t0 << 8) + s;
            atomicAdd(outb + (l - PAD), acc * TW3);
        }
    } else {
        // batch start: l in [384, 768), env varies
        if (tid < 384) {
            int l = PAD + tid;
            int tmax = l >> 8;             // 1 or 2
            float acc = 0.0f, env = 0.0f;
            for (int t = 0; t <= tmax; t++) {
                int pos = l - (t << 8);
                float wv = __ldg(win + pos);
                env = fmaf(wv, wv, env);
                acc += y[t * YPITCH + pos];
            }
            outb[l - PAD] = acc / env;
        }
    }

    if (t0 != 2040) {
        // top stripe: l in [256(t0+8), 256(t0+11))
        #pragma unroll
        for (int s = tid; s < 768; s += 512) {
            int r = s >> 8;                // 0,1,2 ; count = 3 - r
            float acc = y[7 * YPITCH + s + 256];
            if (r <= 1) acc += y[6 * YPITCH + s + 512];
            if (r == 0) acc += y[5 * YPITCH + s + 768];
            int l = ((t0 + 8) << 8) + s;
            atomicAdd(outb + (l - PAD), acc * TW3);
        }
    } else {
        // batch end: l in [524288, 524672)
        if (tid < 384) {
            int l = 524288 + tid;
            int tmin = (l - 768) >> 8;     // 2045..2046
            float acc = 0.0f, env = 0.0f;
            for (int t = tmin; t <= 2047; t++) {
                int pos = l - (t << 8);
                float wv = __ldg(win + pos);
                env = fmaf(wv, wv, env);
                acc += y[(t - 2040) * YPITCH + pos];
            }
            outb[l - PAD] = acc / env;
        }
    }
}

extern "C" void kernel_launch(void* const* d_in, const int* in_sizes, int n_in,
                              void* d_out, int out_size)
{
    const float* spr = (const float*)d_in[0];
    const float* spi = (const float*)d_in[1];
    const float* win = (const float*)d_in[2];
    float* out = (float*)d_out;

    cudaFuncSetAttribute(istft_fused_kernel,
                         cudaFuncAttributeMaxDynamicSharedMemorySize, SM_BYTES);

    istft_zero_kernel<<<3072, 256>>>((float4*)out);
    istft_fused_kernel<<<NFRAMES / FPB, 512, SM_BYTES>>>(spr, spi, win, out);
}